// round 12
// baseline (speedup 1.0000x reference)
#include <cuda_runtime.h>
#include <cuda_bf16.h>
#include <cstdint>
#include <math.h>

// Problem constants (CTC_72000831750194): B=32, T=1000, V=1024, L=128
#define CB 32
#define CT 1000
#define CV 1024
#define CL 128
#define CS (2 * CL + 1)   // 257
#define PSTR 132          // per-(b,t) row: [p_blank, pad, pad, pad, p_lab0..p_lab127]
#define FULLM 0xffffffffu

// Scratch (allocation-free rule: __device__ globals)
__device__ float g_p[(size_t)CB * CT * PSTR];
__device__ float g_loss[CB];

// ---------------------------------------------------------------------------
// Kernel 1: warp-per-row softmax (stable since R3: ~26us, ~68% DRAM).
// ---------------------------------------------------------------------------
__global__ void __launch_bounds__(256) ctc_p_kernel(
    const float* __restrict__ hs, const int* __restrict__ ys)
{
    const int warp = threadIdx.x >> 5;
    const int lane = threadIdx.x & 31;
    const int row  = blockIdx.x * 8 + warp;      // grid = B*T/8
    const int b    = row / CT;

    const float*  rp  = hs + (size_t)row * CV;
    const float4* rp4 = reinterpret_cast<const float4*>(rp);

    float4 v[8];
    #pragma unroll
    for (int i = 0; i < 8; ++i) v[i] = rp4[i * 32 + lane];

    float m = -1e30f;
    #pragma unroll
    for (int i = 0; i < 8; ++i)
        m = fmaxf(m, fmaxf(fmaxf(v[i].x, v[i].y), fmaxf(v[i].z, v[i].w)));
    #pragma unroll
    for (int o = 16; o > 0; o >>= 1)
        m = fmaxf(m, __shfl_xor_sync(FULLM, m, o));

    float s = 0.f;
    #pragma unroll
    for (int i = 0; i < 8; ++i)
        s += __expf(v[i].x - m) + __expf(v[i].y - m) +
             __expf(v[i].z - m) + __expf(v[i].w - m);
    #pragma unroll
    for (int o = 16; o > 0; o >>= 1)
        s += __shfl_xor_sync(FULLM, s, o);

    const float inv = 1.0f / s;

    float* op = g_p + (size_t)row * PSTR;
    #pragma unroll
    for (int c = 0; c < 4; ++c) {
        const int k   = c * 32 + lane;
        const int lab = ys[b * CL + k];
        op[4 + k] = __expf(rp[lab] - m) * inv;
    }
    if (lane == 0) op[0] = __expf(rp[0] - m) * inv;
}

// ---------------------------------------------------------------------------
// Kernel 2: alpha recursion — proven per-batch math, BIT-IDENTICAL trajectory
// to R6-R11 (same step order, renorm after every 4th step, anchor ~2^118).
// R12: TWO independent batch chains interleaved per warp (16 blocks x 32thr).
// Chain B's arithmetic hides chain A's SHFL/REDUX/LDG latency and vice-versa.
// Lane l owns states 8l..8l+7 (a[0..7]); lane 31 also owns state 256 (a[8]).
// ---------------------------------------------------------------------------
__device__ __forceinline__ void step_fwd(
    float a[9], float4 pl, float pbk, const float mk[4], int lane)
{
    float s1 = __shfl_up_sync(FULLM, a[7], 1);   // old state 8l-1
    if (lane == 0) s1 = 0.f;

    const float n0 = (a[0] + s1) * pbk;
    const float n1 = fmaf(mk[0], s1,   a[1] + a[0]) * pl.x;
    const float n2 = (a[2] + a[1]) * pbk;
    const float n3 = fmaf(mk[1], a[1], a[3] + a[2]) * pl.y;
    const float n4 = (a[4] + a[3]) * pbk;
    const float n5 = fmaf(mk[2], a[3], a[5] + a[4]) * pl.z;
    const float n6 = (a[6] + a[5]) * pbk;
    const float n7 = fmaf(mk[3], a[5], a[7] + a[6]) * pl.w;
    const float n8 = (a[8] + a[7]) * pbk;        // state 256 on lane 31
    a[0] = n0; a[1] = n1; a[2] = n2; a[3] = n3; a[4] = n4;
    a[5] = n5; a[6] = n6; a[7] = n7; a[8] = n8;
}

// renorm warp max to biased exponent 245 (~2^118); exact power-of-two scale.
#define RENORM(a, Eacc)                                                       \
{                                                                             \
    const float _m01 = fmaxf(a[0], a[1]);                                     \
    const float _m23 = fmaxf(a[2], a[3]);                                     \
    const float _m45 = fmaxf(a[4], a[5]);                                     \
    const float _m67 = fmaxf(a[6], a[7]);                                     \
    const float _m03 = fmaxf(_m01, _m23);                                     \
    const float _m47 = fmaxf(_m45, _m67);                                     \
    const float _m   = fmaxf(fmaxf(_m03, _m47), a[8]);                        \
    const int _e = (int)(__reduce_max_sync(FULLM, __float_as_uint(_m)) >> 23);\
    if (_e > 0) {                                                             \
        const int _d = 245 - _e;                                              \
        if (_d <= 127) {                                                      \
            const float _sc = __uint_as_float((unsigned)(_d + 127) << 23);    \
            _Pragma("unroll")                                                 \
            for (int _j = 0; _j < 9; ++_j) a[_j] *= _sc;                      \
        } else {                                                              \
            const int _d1 = _d >> 1;                                          \
            const float _s1 = __uint_as_float((unsigned)(_d1 + 127) << 23);   \
            const float _s2 = __uint_as_float((unsigned)(_d - _d1 + 127) << 23);\
            _Pragma("unroll")                                                 \
            for (int _j = 0; _j < 9; ++_j) a[_j] = (a[_j] * _s1) * _s2;       \
        }                                                                     \
        Eacc -= _d;                                                           \
    }                                                                         \
}

__global__ void __launch_bounds__(32) ctc_alpha2_kernel(
    const int* __restrict__ h_lens, const int* __restrict__ ys,
    const int* __restrict__ ys_lens)
{
    const int blk  = blockIdx.x;            // grid = CB/2
    const int lane = threadIdx.x;
    const int bA = 2 * blk, bB = 2 * blk + 1;

    int TbA = h_lens[bA]; if (TbA > CT) TbA = CT;
    int TbB = h_lens[bB]; if (TbB > CT) TbB = CT;
    const float* pA = g_p + (size_t)bA * CT * PSTR;
    const float* pB = g_p + (size_t)bB * CT * PSTR;

    // skip masks per chain: odd state s=2k+1 skips iff k>=1 && ys[k]!=ys[k-1]
    float mkA[4], mkB[4];
    #pragma unroll
    for (int j = 0; j < 4; ++j) {
        const int k = 4 * lane + j;
        mkA[j] = (k >= 1 && ys[bA * CL + k] != ys[bA * CL + k - 1]) ? 1.f : 0.f;
        mkB[j] = (k >= 1 && ys[bB * CL + k] != ys[bB * CL + k - 1]) ? 1.f : 0.f;
    }

    // alpha at t=0
    float aA[9], aB[9];
    #pragma unroll
    for (int j = 0; j < 9; ++j) { aA[j] = 0.f; aB[j] = 0.f; }
    if (lane == 0) {
        aA[0] = pA[0]; aA[1] = pA[4];
        aB[0] = pB[0]; aB[1] = pB[4];
    }
    int EA = 0, EB = 0;

    #define LR(P, st, PL, PB_)                                                \
    {                                                                         \
        int _t = (st); if (_t > CT - 1) _t = CT - 1;                          \
        const float* _r = (P) + (size_t)_t * PSTR;                            \
        PL = reinterpret_cast<const float4*>(_r + 4)[lane];                   \
        PB_ = _r[0];                                                          \
    }

    // double-buffered 4-row chunks per chain
    float4 L0A[4], L1A[4], L0B[4], L1B[4];
    float  C0A[4], C1A[4], C0B[4], C1B[4];
    #pragma unroll
    for (int k = 0; k < 4; ++k) {
        LR(pA, 1 + k, L0A[k], C0A[k]);  LR(pB, 1 + k, L0B[k], C0B[k]);
    }
    #pragma unroll
    for (int k = 0; k < 4; ++k) {
        LR(pA, 5 + k, L1A[k], C1A[k]);  LR(pB, 5 + k, L1B[k], C1B[k]);
    }

    // fast phase: 4 steps (all valid), refill consumed slot right after use
    // (rows S+8..S+11), renorm after the 4th step (same cadence as R6-R11).
    #define PH_FAST(LA_, CA_, LB_, CB_, S)                                    \
    {                                                                         \
        _Pragma("unroll")                                                     \
        for (int _k = 0; _k < 4; ++_k) {                                      \
            step_fwd(aA, LA_[_k], CA_[_k], mkA, lane);                        \
            step_fwd(aB, LB_[_k], CB_[_k], mkB, lane);                        \
            LR(pA, (S) + 8 + _k, LA_[_k], CA_[_k]);                           \
            LR(pB, (S) + 8 + _k, LB_[_k], CB_[_k]);                           \
        }                                                                     \
        RENORM(aA, EA);                                                       \
        RENORM(aB, EB);                                                       \
    }

    // tail phase: per-chain per-step guards, same renorm cadence
    #define PH_TAIL(LA_, CA_, LB_, CB_, S)                                    \
    {                                                                         \
        _Pragma("unroll")                                                     \
        for (int _k = 0; _k < 4; ++_k) {                                      \
            if ((S) + _k < TbA) step_fwd(aA, LA_[_k], CA_[_k], mkA, lane);    \
            if ((S) + _k < TbB) step_fwd(aB, LB_[_k], CB_[_k], mkB, lane);    \
            LR(pA, (S) + 8 + _k, LA_[_k], CA_[_k]);                           \
            LR(pB, (S) + 8 + _k, LB_[_k], CB_[_k]);                           \
        }                                                                     \
        RENORM(aA, EA);                                                       \
        RENORM(aB, EB);                                                       \
    }

    const int Tmin = (TbA < TbB) ? TbA : TbB;
    const int Tmax = (TbA > TbB) ? TbA : TbB;

    int t0 = 1;
    for (; t0 + 8 <= Tmin; t0 += 8) {
        PH_FAST(L0A, C0A, L0B, C0B, t0)
        PH_FAST(L1A, C1A, L1B, C1B, t0 + 4)
    }
    for (; t0 < Tmax; t0 += 8) {
        PH_TAIL(L0A, C0A, L0B, C0B, t0)
        PH_TAIL(L1A, C1A, L1B, C1B, t0 + 4)
    }
    #undef PH_FAST
    #undef PH_TAIL
    #undef LR

    // final: loss_c = -( log(alpha[2L]) (+) log(alpha[2L-1]) ) / L per chain
    __shared__ float smA[CS], smB[CS];
    #pragma unroll
    for (int j = 0; j < 8; ++j) {
        smA[8 * lane + j] = aA[j];
        smB[8 * lane + j] = aB[j];
    }
    if (lane == 31) { smA[256] = aA[8]; smB[256] = aB[8]; }
    __syncwarp();
    if (lane == 0) {
        const double LN2 = 0.6931471805599453;
        {
            const int s_b = 2 * ys_lens[bA], s_l = s_b - 1;
            const float mb = smA[s_b], ml = smA[s_l];
            const double E = (double)EA * LN2;
            double la = (mb > 0.f) ? log((double)mb) + E : -1e300;
            double lb = (ml > 0.f) ? log((double)ml) + E : -1e300;
            const double mx = fmax(la, lb);
            g_loss[bA] = (float)(-(mx + log(exp(la - mx) + exp(lb - mx)))
                                 / (double)ys_lens[bA]);
        }
        {
            const int s_b = 2 * ys_lens[bB], s_l = s_b - 1;
            const float mb = smB[s_b], ml = smB[s_l];
            const double E = (double)EB * LN2;
            double la = (mb > 0.f) ? log((double)mb) + E : -1e300;
            double lb = (ml > 0.f) ? log((double)ml) + E : -1e300;
            const double mx = fmax(la, lb);
            g_loss[bB] = (float)(-(mx + log(exp(la - mx) + exp(lb - mx)))
                                 / (double)ys_lens[bB]);
        }
    }
}

// ---------------------------------------------------------------------------
// Kernel 3: mean over batch -> scalar output
// ---------------------------------------------------------------------------
__global__ void ctc_reduce_kernel(float* __restrict__ out)
{
    float v = (threadIdx.x < CB) ? g_loss[threadIdx.x] : 0.f;
    #pragma unroll
    for (int o = 16; o > 0; o >>= 1)
        v += __shfl_xor_sync(FULLM, v, o);
    if (threadIdx.x == 0) out[0] = v / (float)CB;
}

extern "C" void kernel_launch(void* const* d_in, const int* in_sizes, int n_in,
                              void* d_out, int out_size)
{
    const float* hs      = (const float*)d_in[0];  // (B, T, V)
    const int*   h_lens  = (const int*)  d_in[1];  // (B,)
    const int*   ys      = (const int*)  d_in[2];  // (B, L)
    const int*   ys_lens = (const int*)  d_in[3];  // (B,)
    float*       out     = (float*)      d_out;

    ctc_p_kernel<<<CB * CT / 8, 256>>>(hs, ys);
    ctc_alpha2_kernel<<<CB / 2, 32>>>(h_lens, ys, ys_lens);
    ctc_reduce_kernel<<<1, 32>>>(out);
}

// round 14
// speedup vs baseline: 1.5482x; 1.5482x over previous
#include <cuda_runtime.h>
#include <cuda_bf16.h>
#include <cstdint>
#include <math.h>

// Problem constants (CTC_72000831750194): B=32, T=1000, V=1024, L=128
#define CB 32
#define CT 1000
#define CV 1024
#define CL 128
#define CS (2 * CL + 1)   // 257
#define PSTR 132          // per-(b,t) row: [p_blank, pad, pad, pad, p_lab0..p_lab127]
#define FULLM 0xffffffffu

// Scratch (allocation-free rule: __device__ globals)
__device__ float g_p[(size_t)CB * CT * PSTR];
__device__ float g_loss[CB];

// ---------------------------------------------------------------------------
// Kernel 1: warp-per-row softmax (stable since R3: ~26us, ~68% DRAM).
// ---------------------------------------------------------------------------
__global__ void __launch_bounds__(256) ctc_p_kernel(
    const float* __restrict__ hs, const int* __restrict__ ys)
{
    const int warp = threadIdx.x >> 5;
    const int lane = threadIdx.x & 31;
    const int row  = blockIdx.x * 8 + warp;      // grid = B*T/8
    const int b    = row / CT;

    const float*  rp  = hs + (size_t)row * CV;
    const float4* rp4 = reinterpret_cast<const float4*>(rp);

    float4 v[8];
    #pragma unroll
    for (int i = 0; i < 8; ++i) v[i] = rp4[i * 32 + lane];

    float m = -1e30f;
    #pragma unroll
    for (int i = 0; i < 8; ++i)
        m = fmaxf(m, fmaxf(fmaxf(v[i].x, v[i].y), fmaxf(v[i].z, v[i].w)));
    #pragma unroll
    for (int o = 16; o > 0; o >>= 1)
        m = fmaxf(m, __shfl_xor_sync(FULLM, m, o));

    float s = 0.f;
    #pragma unroll
    for (int i = 0; i < 8; ++i)
        s += __expf(v[i].x - m) + __expf(v[i].y - m) +
             __expf(v[i].z - m) + __expf(v[i].w - m);
    #pragma unroll
    for (int o = 16; o > 0; o >>= 1)
        s += __shfl_xor_sync(FULLM, s, o);

    const float inv = 1.0f / s;

    float* op = g_p + (size_t)row * PSTR;
    #pragma unroll
    for (int c = 0; c < 4; ++c) {
        const int k   = c * 32 + lane;
        const int lab = ys[b * CL + k];
        op[4 + k] = __expf(rp[lab] - m) * inv;
    }
    if (lane == 0) op[0] = __expf(rp[0] - m) * inv;
}

// ---------------------------------------------------------------------------
// Kernel 2: alpha recursion — proven math, BIT-IDENTICAL trajectory to
// R6/R9/R10/R11 (same step order, renorm after every 4th step, anchor ~2^118;
// all scalings are exact powers of two, so folding a scale into the next
// step's p-values commutes exactly).
// One warp per batch element. Lane l owns states 8l..8l+7 (a[0..7]); lane 31
// also owns state 256 (a[8]).
// R13: fast loop uses immediate-offset LDGs from 2 advancing pointers (no
// per-load IMAD/clamp), and the mid-group renorm folds its scale into the
// next step's probabilities (takes REDUX+scale off the critical path).
// ---------------------------------------------------------------------------
__device__ __forceinline__ void step_fwd(
    float a[9], float4 pl, float pbk, const float mk[4], int lane)
{
    float s1 = __shfl_up_sync(FULLM, a[7], 1);   // old state 8l-1
    if (lane == 0) s1 = 0.f;

    const float n0 = (a[0] + s1) * pbk;
    const float n1 = fmaf(mk[0], s1,   a[1] + a[0]) * pl.x;
    const float n2 = (a[2] + a[1]) * pbk;
    const float n3 = fmaf(mk[1], a[1], a[3] + a[2]) * pl.y;
    const float n4 = (a[4] + a[3]) * pbk;
    const float n5 = fmaf(mk[2], a[3], a[5] + a[4]) * pl.z;
    const float n6 = (a[6] + a[5]) * pbk;
    const float n7 = fmaf(mk[3], a[5], a[7] + a[6]) * pl.w;
    const float n8 = (a[8] + a[7]) * pbk;        // state 256 on lane 31
    a[0] = n0; a[1] = n1; a[2] = n2; a[3] = n3; a[4] = n4;
    a[5] = n5; a[6] = n6; a[7] = n7; a[8] = n8;
}

// tree-local max + warp REDUX -> biased exponent _e of warp max
#define WMAXE(a, EVAR)                                                        \
    const float _m01 = fmaxf(a[0], a[1]);                                     \
    const float _m23 = fmaxf(a[2], a[3]);                                     \
    const float _m45 = fmaxf(a[4], a[5]);                                     \
    const float _m67 = fmaxf(a[6], a[7]);                                     \
    const float _m03 = fmaxf(_m01, _m23);                                     \
    const float _m47 = fmaxf(_m45, _m67);                                     \
    const float _m   = fmaxf(fmaxf(_m03, _m47), a[8]);                        \
    const int EVAR = (int)(__reduce_max_sync(FULLM, __float_as_uint(_m)) >> 23);

// classic renorm: scale the states to anchor biased-exp 245 (~2^118)
#define RENORM(a, Eacc)                                                       \
{                                                                             \
    WMAXE(a, _e)                                                              \
    if (_e > 0) {                                                             \
        const int _d = 245 - _e;                                              \
        if (_d <= 127) {                                                      \
            const float _sc = __uint_as_float((unsigned)(_d + 127) << 23);    \
            _Pragma("unroll")                                                 \
            for (int _j = 0; _j < 9; ++_j) a[_j] *= _sc;                      \
        } else {                                                              \
            const int _d1 = _d >> 1;                                          \
            const float _s1 = __uint_as_float((unsigned)(_d1 + 127) << 23);   \
            const float _s2 = __uint_as_float((unsigned)(_d - _d1 + 127) << 23);\
            _Pragma("unroll")                                                 \
            for (int _j = 0; _j < 9; ++_j) a[_j] = (a[_j] * _s1) * _s2;       \
        }                                                                     \
        Eacc -= _d;                                                           \
    }                                                                         \
}

// folded renorm: apply the (exact pow2) scale to the NEXT step's p-values
// instead of the 9 states — bit-identical product, but the next step's sums
// overlap the REDUX latency. Fallback to classic for large transient d
// (avoids p overflow; only the first renorm after t=0 can hit this).
#define RENORM_FOLD(a, Eacc, PLn, PBn)                                        \
{                                                                             \
    WMAXE(a, _e)                                                              \
    if (_e > 0) {                                                             \
        const int _d = 245 - _e;                                              \
        if (_d <= 64 && _d >= -64) {                                          \
            const float _sc = __uint_as_float((unsigned)(_d + 127) << 23);    \
            PLn.x *= _sc; PLn.y *= _sc; PLn.z *= _sc; PLn.w *= _sc;           \
            PBn   *= _sc;                                                     \
        } else {                                                              \
            const int _d1 = _d >> 1;                                          \
            const float _s1 = __uint_as_float((unsigned)(_d1 + 127) << 23);   \
            const float _s2 = __uint_as_float((unsigned)(_d - _d1 + 127) << 23);\
            _Pragma("unroll")                                                 \
            for (int _j = 0; _j < 9; ++_j) a[_j] = (a[_j] * _s1) * _s2;       \
        }                                                                     \
        Eacc -= _d;                                                           \
    }                                                                         \
}

__global__ void __launch_bounds__(32) ctc_alpha_kernel(
    const int* __restrict__ h_lens, const int* __restrict__ ys,
    const int* __restrict__ ys_lens)
{
    const int b    = blockIdx.x;
    const int lane = threadIdx.x;
    int Tb = h_lens[b];
    if (Tb > CT) Tb = CT;
    const float* pb = g_p + (size_t)b * CT * PSTR;

    // skip masks: odd state s=2k+1 skips iff k>=1 && ys[k]!=ys[k-1]
    float mk[4];
    #pragma unroll
    for (int j = 0; j < 4; ++j) {
        const int k = 4 * lane + j;
        mk[j] = (k >= 1 && ys[b * CL + k] != ys[b * CL + k - 1]) ? 1.f : 0.f;
    }

    // alpha at t=0
    float a[9];
    #pragma unroll
    for (int j = 0; j < 9; ++j) a[j] = 0.f;
    if (lane == 0) { a[0] = pb[0]; a[1] = pb[4]; }

    int Eacc = 0;   // true = stored * 2^Eacc (identical in every lane)

    // clamped generic row load (preload + tail only)
    #define LOADROW(st, PL, PB_)                                              \
    {                                                                         \
        int _t = (st); if (_t > CT - 1) _t = CT - 1;                          \
        const float* _r = pb + (size_t)_t * PSTR;                             \
        PL = reinterpret_cast<const float4*>(_r + 4)[lane];                   \
        PB_ = _r[0];                                                          \
    }

    // 3 buffers used in rotating ROLES (no data movement between them)
    float4 L0[8], L1[8], L2[8];
    float  B0[8], B1[8], B2[8];
    #pragma unroll
    for (int k = 0; k < 8; ++k) LOADROW(1 + k, L0[k], B0[k]);
    #pragma unroll
    for (int k = 0; k < 8; ++k) LOADROW(9 + k, L1[k], B1[k]);

    // fast-path base pointers for row t0 (advanced by one IADD per chunk)
    const float* pbase  = pb + (size_t)1 * PSTR;   // &row[t0][0]
    const float* plane4 = pbase + 4 + lane * 4;    // &row[t0][4 + 4*lane]

    // fast load: row t0 + OFFR, compile-time OFFR -> immediate-offset LDGs
    #define LRF(OFFR, PL, PB_)                                                \
    {                                                                         \
        PL = *reinterpret_cast<const float4*>(plane4 + (OFFR) * PSTR);        \
        PB_ = *(pbase + (OFFR) * PSTR);                                       \
    }

    // fast phase: prefetch rows (SOFF+16..SOFF+23) rel. t0, 8 unguarded
    // steps; renorm after step 4 FOLDED into slot 4's p, after step 8 classic.
    #define PHASE_FAST(CL_, CB_, PL_, PB_, SOFF)                              \
    {                                                                         \
        _Pragma("unroll")                                                     \
        for (int _k = 0; _k < 8; ++_k) LRF((SOFF) + 16 + _k, PL_[_k], PB_[_k]); \
        step_fwd(a, CL_[0], CB_[0], mk, lane);                                \
        step_fwd(a, CL_[1], CB_[1], mk, lane);                                \
        step_fwd(a, CL_[2], CB_[2], mk, lane);                                \
        step_fwd(a, CL_[3], CB_[3], mk, lane);                                \
        RENORM_FOLD(a, Eacc, CL_[4], CB_[4]);                                 \
        step_fwd(a, CL_[4], CB_[4], mk, lane);                                \
        step_fwd(a, CL_[5], CB_[5], mk, lane);                                \
        step_fwd(a, CL_[6], CB_[6], mk, lane);                                \
        step_fwd(a, CL_[7], CB_[7], mk, lane);                                \
        RENORM(a, Eacc);                                                      \
    }

    // guarded tail phase (clamped loads, per-step guards, classic renorms)
    #define PHASE_TAIL(CL_, CB_, PL_, PB_, S)                                 \
    {                                                                         \
        _Pragma("unroll")                                                     \
        for (int _k = 0; _k < 8; ++_k) LOADROW((S) + 16 + _k, PL_[_k], PB_[_k]); \
        _Pragma("unroll")                                                     \
        for (int _k = 0; _k < 8; ++_k) {                                      \
            if ((S) + _k < Tb) step_fwd(a, CL_[_k], CB_[_k], mk, lane);       \
            if (_k == 3 || _k == 7) RENORM(a, Eacc);                          \
        }                                                                     \
    }

    int t0 = 1;
    // fast loop: consumed t0..t0+23 < Tb and prefetched t0+16..t0+39 < Tb
    for (; t0 + 48 <= Tb; t0 += 24) {
        PHASE_FAST(L0, B0, L2, B2, 0)
        PHASE_FAST(L1, B1, L0, B0, 8)
        PHASE_FAST(L2, B2, L1, B1, 16)
        pbase  += 24 * PSTR;
        plane4 += 24 * PSTR;
    }
    for (; t0 < Tb; t0 += 24) {
        PHASE_TAIL(L0, B0, L2, B2, t0)
        PHASE_TAIL(L1, B1, L0, B0, t0 + 8)
        PHASE_TAIL(L2, B2, L1, B1, t0 + 16)
    }
    #undef PHASE_FAST
    #undef PHASE_TAIL
    #undef LRF
    #undef LOADROW

    // final: loss = -( log(alpha[2L]) (+) log(alpha[2L-1]) ) / L
    __shared__ float sm[CS];
    #pragma unroll
    for (int j = 0; j < 8; ++j) sm[8 * lane + j] = a[j];
    if (lane == 31) sm[256] = a[8];
    __syncwarp();
    if (lane == 0) {
        const int s_b = 2 * ys_lens[b];
        const int s_l = s_b - 1;
        const float mb = sm[s_b], ml = sm[s_l];
        const double LN2 = 0.6931471805599453;
        const double E  = (double)Eacc * LN2;
        double la = (mb > 0.f) ? log((double)mb) + E : -1e300;
        double lb = (ml > 0.f) ? log((double)ml) + E : -1e300;
        const double mx  = fmax(la, lb);
        const double res = mx + log(exp(la - mx) + exp(lb - mx));
        g_loss[b] = (float)(-res / (double)ys_lens[b]);
    }
}

// ---------------------------------------------------------------------------
// Kernel 3: mean over batch -> scalar output
// ---------------------------------------------------------------------------
__global__ void ctc_reduce_kernel(float* __restrict__ out)
{
    float v = (threadIdx.x < CB) ? g_loss[threadIdx.x] : 0.f;
    #pragma unroll
    for (int o = 16; o > 0; o >>= 1)
        v += __shfl_xor_sync(FULLM, v, o);
    if (threadIdx.x == 0) out[0] = v / (float)CB;
}

extern "C" void kernel_launch(void* const* d_in, const int* in_sizes, int n_in,
                              void* d_out, int out_size)
{
    const float* hs      = (const float*)d_in[0];  // (B, T, V)
    const int*   h_lens  = (const int*)  d_in[1];  // (B,)
    const int*   ys      = (const int*)  d_in[2];  // (B, L)
    const int*   ys_lens = (const int*)  d_in[3];  // (B,)
    float*       out     = (float*)      d_out;

    ctc_p_kernel<<<CB * CT / 8, 256>>>(hs, ys);
    ctc_alpha_kernel<<<CB, 32>>>(h_lens, ys, ys_lens);
    ctc_reduce_kernel<<<1, 32>>>(out);
}